// round 1
// baseline (speedup 1.0000x reference)
#include <cuda_runtime.h>
#include <math.h>

// Problem constants (Attention_33492154974379): x [B,T,D] fp32
#define BATCH 8
#define SEQ   2048
#define DIM   1024

// GEMM tiling
#define BM 128
#define BN 128
#define BK 16
#define TPB 256

// ---------------------------------------------------------------------------
// Kernel 1: S[b,i,j] = dot(x[b,i,:], x[b,j,:])  -- lower-triangular tiles only
// Raw scores written into the weights region (overwritten/normalized by K2).
// ---------------------------------------------------------------------------
__global__ __launch_bounds__(TPB) void gemm_scores(const float* __restrict__ x,
                                                   float* __restrict__ Sg) {
    const int b  = blockIdx.z;
    const int it = blockIdx.y;
    const int jt = blockIdx.x;
    if (jt > it) return;  // strictly-upper tiles never read

    const float* X  = x  + (size_t)b * SEQ * DIM;
    float*       Sb = Sg + (size_t)b * SEQ * SEQ;

    __shared__ float As[BK][BM + 4];
    __shared__ float Bs[BK][BN + 4];

    const int tid = threadIdx.x;
    const int tm  = tid / 16;       // 0..15
    const int tn  = tid % 16;       // 0..15

    const int i0 = it * BM;
    const int j0 = jt * BN;

    // Global load mapping: 128x16 tile, 256 threads, 2x float4 each
    const int lr = tid / 4;          // 0..63
    const int lc = (tid % 4) * 4;    // 0,4,8,12

    float acc[8][8];
#pragma unroll
    for (int u = 0; u < 8; u++)
#pragma unroll
        for (int v = 0; v < 8; v++) acc[u][v] = 0.f;

    for (int k0 = 0; k0 < DIM; k0 += BK) {
        float4 a0 = *(const float4*)&X[(size_t)(i0 + lr)      * DIM + k0 + lc];
        float4 a1 = *(const float4*)&X[(size_t)(i0 + lr + 64) * DIM + k0 + lc];
        float4 b0 = *(const float4*)&X[(size_t)(j0 + lr)      * DIM + k0 + lc];
        float4 b1 = *(const float4*)&X[(size_t)(j0 + lr + 64) * DIM + k0 + lc];
        __syncthreads();
        As[lc + 0][lr] = a0.x; As[lc + 1][lr] = a0.y; As[lc + 2][lr] = a0.z; As[lc + 3][lr] = a0.w;
        As[lc + 0][lr + 64] = a1.x; As[lc + 1][lr + 64] = a1.y; As[lc + 2][lr + 64] = a1.z; As[lc + 3][lr + 64] = a1.w;
        Bs[lc + 0][lr] = b0.x; Bs[lc + 1][lr] = b0.y; Bs[lc + 2][lr] = b0.z; Bs[lc + 3][lr] = b0.w;
        Bs[lc + 0][lr + 64] = b1.x; Bs[lc + 1][lr + 64] = b1.y; Bs[lc + 2][lr + 64] = b1.z; Bs[lc + 3][lr + 64] = b1.w;
        __syncthreads();

#pragma unroll
        for (int k = 0; k < BK; k++) {
            float ra[8], rb[8];
            *(float4*)&ra[0] = *(const float4*)&As[k][tm * 4];
            *(float4*)&ra[4] = *(const float4*)&As[k][64 + tm * 4];
            *(float4*)&rb[0] = *(const float4*)&Bs[k][tn * 4];
            *(float4*)&rb[4] = *(const float4*)&Bs[k][64 + tn * 4];
#pragma unroll
            for (int u = 0; u < 8; u++)
#pragma unroll
                for (int v = 0; v < 8; v++) acc[u][v] += ra[u] * rb[v];
        }
    }

#pragma unroll
    for (int u = 0; u < 8; u++) {
        int r = i0 + ((u < 4) ? (tm * 4 + u) : (60 + tm * 4 + u));
        float4 c0 = make_float4(acc[u][0], acc[u][1], acc[u][2], acc[u][3]);
        float4 c1 = make_float4(acc[u][4], acc[u][5], acc[u][6], acc[u][7]);
        *(float4*)&Sb[(size_t)r * SEQ + j0 + tn * 4]      = c0;
        *(float4*)&Sb[(size_t)r * SEQ + j0 + 64 + tn * 4] = c1;
    }
}

// ---------------------------------------------------------------------------
// Kernel 2: in-place row softmax with strict-lower causal mask.
//   row i>0 : w[j] = exp(s[j]-m)/l for j<i, 0 for j>=i
//   row 0   : uniform 1/T  (all entries were -1e9 -> softmax uniform)
// One block (256 thr) per row; 8 values/thread in registers.
// ---------------------------------------------------------------------------
__global__ __launch_bounds__(256) void softmax_rows(float* __restrict__ Wg) {
    const int i = blockIdx.x;
    const int b = blockIdx.y;
    float* row = Wg + ((size_t)b * SEQ + i) * SEQ;
    const int tid = threadIdx.x;

    if (i == 0) {
        const float v = 1.0f / (float)SEQ;
#pragma unroll
        for (int s = 0; s < 8; s++) row[tid + s * 256] = v;
        return;
    }

    float vals[8];
    float m = -3.0e38f;
#pragma unroll
    for (int s = 0; s < 8; s++) {
        int j = tid + s * 256;
        float v = (j < i) ? row[j] : -3.0e38f;
        vals[s] = v;
        m = fmaxf(m, v);
    }

    __shared__ float sred[8];
#pragma unroll
    for (int o = 16; o; o >>= 1) m = fmaxf(m, __shfl_xor_sync(0xffffffffu, m, o));
    if ((tid & 31) == 0) sred[tid >> 5] = m;
    __syncthreads();
    m = sred[0];
#pragma unroll
    for (int w = 1; w < 8; w++) m = fmaxf(m, sred[w]);

    float l = 0.f;
#pragma unroll
    for (int s = 0; s < 8; s++) {
        int j = tid + s * 256;
        float e = (j < i) ? __expf(vals[s] - m) : 0.f;
        vals[s] = e;
        l += e;
    }
#pragma unroll
    for (int o = 16; o; o >>= 1) l += __shfl_xor_sync(0xffffffffu, l, o);
    __syncthreads();
    if ((tid & 31) == 0) sred[tid >> 5] = l;
    __syncthreads();
    l = 0.f;
#pragma unroll
    for (int w = 0; w < 8; w++) l += sred[w];

    const float inv = 1.0f / l;
#pragma unroll
    for (int s = 0; s < 8; s++) row[tid + s * 256] = vals[s] * inv;
}

// ---------------------------------------------------------------------------
// Kernel 3: O = W @ X.   K-loop bounded at (it+1)*BM: all rows in the tile
// have zero weights beyond that (row 0 handled by row0_mean afterwards).
// ---------------------------------------------------------------------------
__global__ __launch_bounds__(TPB) void gemm_av(const float* __restrict__ Wg,
                                               const float* __restrict__ x,
                                               float* __restrict__ Og) {
    const int b  = blockIdx.z;
    const int it = blockIdx.y;   // row tile (T)
    const int dt = blockIdx.x;   // col tile (D)

    const float* W  = Wg + (size_t)b * SEQ * SEQ;
    const float* X  = x  + (size_t)b * SEQ * DIM;
    float*       Ob = Og + (size_t)b * SEQ * DIM;

    __shared__ float As[BK][BM + 4];
    __shared__ float Bs[BK][BN + 4];

    const int tid = threadIdx.x;
    const int tm  = tid / 16;
    const int tn  = tid % 16;

    const int i0 = it * BM;
    const int d0 = dt * BN;
    const int kend = (it + 1) * BM;   // weights zero for k >= kend (rows 1..)

    // A loads (BMxBK, transpose into smem)
    const int lrA = tid / 4;
    const int lcA = (tid % 4) * 4;
    // B loads (BKxBN, direct)
    const int lrB = tid / 32;          // 0..7
    const int lcB = (tid % 32) * 4;    // 0..124

    float acc[8][8];
#pragma unroll
    for (int u = 0; u < 8; u++)
#pragma unroll
        for (int v = 0; v < 8; v++) acc[u][v] = 0.f;

    for (int k0 = 0; k0 < kend; k0 += BK) {
        float4 a0 = *(const float4*)&W[(size_t)(i0 + lrA)      * SEQ + k0 + lcA];
        float4 a1 = *(const float4*)&W[(size_t)(i0 + lrA + 64) * SEQ + k0 + lcA];
        float4 b0 = *(const float4*)&X[(size_t)(k0 + lrB)     * DIM + d0 + lcB];
        float4 b1 = *(const float4*)&X[(size_t)(k0 + lrB + 8) * DIM + d0 + lcB];
        __syncthreads();
        As[lcA + 0][lrA] = a0.x; As[lcA + 1][lrA] = a0.y; As[lcA + 2][lrA] = a0.z; As[lcA + 3][lrA] = a0.w;
        As[lcA + 0][lrA + 64] = a1.x; As[lcA + 1][lrA + 64] = a1.y; As[lcA + 2][lrA + 64] = a1.z; As[lcA + 3][lrA + 64] = a1.w;
        *(float4*)&Bs[lrB][lcB]     = b0;
        *(float4*)&Bs[lrB + 8][lcB] = b1;
        __syncthreads();

#pragma unroll
        for (int k = 0; k < BK; k++) {
            float ra[8], rb[8];
            *(float4*)&ra[0] = *(const float4*)&As[k][tm * 4];
            *(float4*)&ra[4] = *(const float4*)&As[k][64 + tm * 4];
            *(float4*)&rb[0] = *(const float4*)&Bs[k][tn * 4];
            *(float4*)&rb[4] = *(const float4*)&Bs[k][64 + tn * 4];
#pragma unroll
            for (int u = 0; u < 8; u++)
#pragma unroll
                for (int v = 0; v < 8; v++) acc[u][v] += ra[u] * rb[v];
        }
    }

#pragma unroll
    for (int u = 0; u < 8; u++) {
        int r = i0 + ((u < 4) ? (tm * 4 + u) : (60 + tm * 4 + u));
        float4 c0 = make_float4(acc[u][0], acc[u][1], acc[u][2], acc[u][3]);
        float4 c1 = make_float4(acc[u][4], acc[u][5], acc[u][6], acc[u][7]);
        *(float4*)&Ob[(size_t)r * DIM + d0 + tn * 4]      = c0;
        *(float4*)&Ob[(size_t)r * DIM + d0 + 64 + tn * 4] = c1;
    }
}

// ---------------------------------------------------------------------------
// Kernel 4: row 0 of each batch: att_vec[b,0,:] = (1/T) * sum_j x[b,j,:]
// (row 0's weights are uniform 1/T over ALL columns; gemm_av's bounded K-loop
//  doesn't cover that, so overwrite here.)
// ---------------------------------------------------------------------------
__global__ __launch_bounds__(256) void row0_mean(const float* __restrict__ x,
                                                 float* __restrict__ Og) {
    const int b = blockIdx.y;
    const int d = blockIdx.x * 256 + threadIdx.x;
    const float* X = x + (size_t)b * SEQ * DIM;
    float s0 = 0.f, s1 = 0.f, s2 = 0.f, s3 = 0.f;
    for (int j = 0; j < SEQ; j += 4) {
        s0 += X[(size_t)(j + 0) * DIM + d];
        s1 += X[(size_t)(j + 1) * DIM + d];
        s2 += X[(size_t)(j + 2) * DIM + d];
        s3 += X[(size_t)(j + 3) * DIM + d];
    }
    Og[(size_t)b * SEQ * DIM + d] = (s0 + s1 + s2 + s3) * (1.0f / (float)SEQ);
}

// ---------------------------------------------------------------------------
extern "C" void kernel_launch(void* const* d_in, const int* in_sizes, int n_in,
                              void* d_out, int out_size) {
    const float* x = (const float*)d_in[0];
    float* out     = (float*)d_out;
    float* att_vec = out;                                   // [B,T,D]
    float* Wg      = out + (size_t)BATCH * SEQ * DIM;       // [B,T,T]

    dim3 g1(SEQ / BN, SEQ / BM, BATCH);
    gemm_scores<<<g1, TPB>>>(x, Wg);

    dim3 g2(SEQ, BATCH);
    softmax_rows<<<g2, 256>>>(Wg);

    dim3 g3(DIM / BN, SEQ / BM, BATCH);
    gemm_av<<<g3, TPB>>>(Wg, x, att_vec);

    dim3 g4(DIM / 256, BATCH);
    row0_mean<<<g4, 256>>>(x, att_vec);
}